// round 12
// baseline (speedup 1.0000x reference)
#include <cuda_runtime.h>
#include <cstdint>
#include <math.h>

// GRU: B=32, S=2048, E=256, H=256, fp32.
// Kernel 1: gate-input GEMMs xg = x @ {Wz,Wr,Wh}.
// Kernel 2: persistent scan, 16 groups x 8-CTA cluster.
//   NEW decomposition: CTA owns a 32-wide K-SLICE (not j-slice).
//   Each thread = one global output column j; computes partial sums over the
//   local k-slice only (h_k / (r*h)_k are locally produced!), pushes ONE b64
//   partial (batches packed in f32x2 lanes) to the owner CTA of column j.
//   Owner warp does an 8-source f32x2 tree-sum + activation. No broadcasts,
//   no intra-CTA k-reduction, no sP staging.

#define SS   2048
#define EE   256
#define HH   256
#define CSZ  8
#define NB   2
#define NT   256
#define NGRP 16
#define GRID (NGRP * CSZ)
#define GM   (32 * 2048)

typedef unsigned long long u64;

__device__ float g_gates[(size_t)3 * GM * HH];   // [g][b*S+t][h]

// ---------------- helpers ----------------
__device__ __forceinline__ uint32_t smem_u32(const void* p) {
    uint32_t a;
    asm("{ .reg .u64 t; cvta.to.shared.u64 t, %1; cvt.u32.u64 %0, t; }"
        : "=r"(a) : "l"(p));
    return a;
}
__device__ __forceinline__ void mbar_init(uint32_t a, uint32_t cnt) {
    asm volatile("mbarrier.init.shared.b64 [%0], %1;" :: "r"(a), "r"(cnt) : "memory");
}
__device__ __forceinline__ void mbar_expect(uint32_t a, uint32_t bytes) {
    asm volatile("mbarrier.arrive.expect_tx.shared.b64 _, [%0], %1;"
                 :: "r"(a), "r"(bytes) : "memory");
}
__device__ __forceinline__ void mbar_wait(uint32_t a, uint32_t parity) {
    asm volatile(
        "{\n\t.reg .pred P1;\n\t"
        "WL_%=:\n\t"
        "mbarrier.try_wait.parity.acquire.cta.shared::cta.b64 P1, [%0], %1, 0x989680;\n\t"
        "@P1 bra.uni WD_%=;\n\t"
        "bra.uni WL_%=;\n\t"
        "WD_%=:\n\t}"
        :: "r"(a), "r"(parity) : "memory");
}
__device__ __forceinline__ void cluster_sync_() {
    asm volatile("barrier.cluster.arrive.aligned;" ::: "memory");
    asm volatile("barrier.cluster.wait.aligned;"  ::: "memory");
}
__device__ __forceinline__ u64 pk(float lo, float hi) {
    u64 r; asm("mov.b64 %0, {%1, %2};" : "=l"(r) : "f"(lo), "f"(hi)); return r;
}
__device__ __forceinline__ float hsum(u64 v) {
    float a, b; asm("mov.b64 {%0, %1}, %2;" : "=f"(a), "=f"(b) : "l"(v));
    return a + b;
}
__device__ __forceinline__ void unpk(u64 v, float& a, float& b) {
    asm("mov.b64 {%0, %1}, %2;" : "=f"(a), "=f"(b) : "l"(v));
}
__device__ __forceinline__ void ffma2(u64& d, u64 a, u64 b) {
    asm("fma.rn.f32x2 %0, %1, %2, %0;" : "+l"(d) : "l"(a), "l"(b));
}
__device__ __forceinline__ u64 addx2(u64 a, u64 b) {
    u64 r; asm("add.rn.f32x2 %0, %1, %2;" : "=l"(r) : "l"(a), "l"(b)); return r;
}
__device__ __forceinline__ void st_async_b64(uint32_t addr, u64 v, uint32_t mbar) {
    asm volatile("st.async.shared::cluster.mbarrier::complete_tx::bytes.b64 "
                 "[%0], %1, [%2];"
                 :: "r"(addr), "l"(v), "r"(mbar) : "memory");
}

// ================= Kernel 1: gate-input GEMMs =================
__global__ void __launch_bounds__(256)
gru_gemm(const float* __restrict__ x, const float* __restrict__ Wz,
         const float* __restrict__ Wr, const float* __restrict__ Wh)
{
    __shared__ float sA[32][128];
    __shared__ float sB[32][64];

    const int mt = blockIdx.x;
    const int gy = blockIdx.y;
    const int g  = gy >> 2, nt = gy & 3;
    const float* W = (g == 0) ? Wz : (g == 1) ? Wr : Wh;
    const int row0 = mt * 128, col0 = nt * 64;

    const int tid = threadIdx.x;
    const int tx = tid & 15;
    const int ty = tid >> 4;

    u64 acc[8][2];
#pragma unroll
    for (int i = 0; i < 8; i++) { acc[i][0] = 0; acc[i][1] = 0; }

    for (int kc = 0; kc < 8; kc++) {
#pragma unroll
        for (int q = 0; q < 4; q++) {
            const int fi = tid + q * 256;
            const int r  = fi >> 3, c = fi & 7;
            const float4 v = *(const float4*)&x[(size_t)(row0 + r) * EE + kc * 32 + c * 4];
            sA[c * 4 + 0][r] = v.x;
            sA[c * 4 + 1][r] = v.y;
            sA[c * 4 + 2][r] = v.z;
            sA[c * 4 + 3][r] = v.w;
        }
#pragma unroll
        for (int q = 0; q < 2; q++) {
            const int fi = tid + q * 256;
            const int r  = fi >> 4, c = fi & 15;
            *(float4*)&sB[r][c * 4] =
                *(const float4*)&W[(size_t)(kc * 32 + r) * HH + col0 + c * 4];
        }
        __syncthreads();
#pragma unroll 8
        for (int k = 0; k < 32; k++) {
            const float4 a0 = *(const float4*)&sA[k][ty * 8];
            const float4 a1 = *(const float4*)&sA[k][ty * 8 + 4];
            const u64 b0 = *(const u64*)&sB[k][tx * 4];
            const u64 b1 = *(const u64*)&sB[k][tx * 4 + 2];
            const float av[8] = {a0.x, a0.y, a0.z, a0.w, a1.x, a1.y, a1.z, a1.w};
#pragma unroll
            for (int i = 0; i < 8; i++) {
                const u64 a2 = pk(av[i], av[i]);
                ffma2(acc[i][0], a2, b0);
                ffma2(acc[i][1], a2, b1);
            }
        }
        __syncthreads();
    }
#pragma unroll
    for (int i = 0; i < 8; i++) {
        const size_t idx = ((size_t)g * GM + row0 + ty * 8 + i) * HH + col0 + tx * 4;
        *(u64*)&g_gates[idx]     = acc[i][0];
        *(u64*)&g_gates[idx + 2] = acc[i][1];
    }
}

// ================= Kernel 2: persistent scan =================
// smem floats:
#define OFF_H    0      // [2 b][32] local h slice
#define OFF_RH   64     // [2 b][32] local r*h slice
#define OFF_PRZ  128    // [2 par][2 gate][32 jl][8 src] u64 = 2048 floats
#define OFF_PH   2176   // [2 par][32 jl][8 src] u64 = 1024 floats
#define OFF_MB   3200   // 4 mbarriers
#define SMEM_FLOATS (OFF_MB + 8)
#define SMEM_BYTES  (SMEM_FLOATS * 4)

extern __shared__ float smem[];

__global__ void __cluster_dims__(CSZ, 1, 1) __launch_bounds__(NT, 1)
gru_scan(const float* __restrict__ h0,
         const float* __restrict__ Uz, const float* __restrict__ Ur,
         const float* __restrict__ Uh, float* __restrict__ out)
{
    const int tid   = threadIdx.x;             // = global output column j
    const int rank  = blockIdx.x & (CSZ - 1);
    const int grp   = blockIdx.x >> 3;
    const int b0    = grp * NB;
    const int kbase = rank * 32;               // this CTA's k-slice
    const int dstr  = tid >> 5;                // owner rank of column j
    const int jl    = tid & 31;                // local column at owner

    float* sH  = smem + OFF_H;
    float* sRH = smem + OFF_RH;

    const uint32_t base_u = smem_u32(smem);
    const uint32_t mb_rz  = base_u + OFF_MB * 4;        // +par*8
    const uint32_t mb_h   = base_u + OFF_MB * 4 + 16;   // +par*8

    // U rows k in [kbase, kbase+32), column j=tid; k-pairs packed for FFMA2.
    u64 uz2[16], ur2[16], uh2[16];
#pragma unroll
    for (int p = 0; p < 16; p++) {
        const int k = kbase + 2 * p;
        uz2[p] = pk(Uz[k * HH + tid], Uz[(k + 1) * HH + tid]);
        ur2[p] = pk(Ur[k * HH + tid], Ur[(k + 1) * HH + tid]);
        uh2[p] = pk(Uh[k * HH + tid], Uh[(k + 1) * HH + tid]);
    }

    // local h slice (owned columns = kbase..kbase+31), kept in warp0 regs + smem
    float hreg0 = 0.f, hreg1 = 0.f;
    if (tid < 32) {
        hreg0 = h0[b0 * HH + kbase + tid];
        hreg1 = h0[(b0 + 1) * HH + kbase + tid];
        sH[tid]      = hreg0;
        sH[32 + tid] = hreg1;
    }
    if (tid == 0) {
        mbar_init(mb_rz, 1); mbar_init(mb_rz + 8, 1);
        mbar_init(mb_h, 1);  mbar_init(mb_h + 8, 1);
    }
    __syncthreads();
    cluster_sync_();

    // fixed destination CTA for this thread's partials
    uint32_t peer;
    asm volatile("mapa.shared::cluster.u32 %0, %1, %2;"
                 : "=r"(peer) : "r"(base_u), "r"(dstr));

    // warp0: gate-input prefetch for its owned columns (j = kbase + lane)
    float pz0 = 0.f, pz1 = 0.f, pr0 = 0.f, pr1 = 0.f, phh0 = 0.f, phh1 = 0.f;
    if (tid < 32) {
        const int jown = kbase + tid;
        pz0  = g_gates[((size_t)0 * GM + (size_t)b0 * SS) * HH + jown];
        pz1  = g_gates[((size_t)0 * GM + (size_t)(b0 + 1) * SS) * HH + jown];
        pr0  = g_gates[((size_t)1 * GM + (size_t)b0 * SS) * HH + jown];
        pr1  = g_gates[((size_t)1 * GM + (size_t)(b0 + 1) * SS) * HH + jown];
        phh0 = g_gates[((size_t)2 * GM + (size_t)b0 * SS) * HH + jown];
        phh1 = g_gates[((size_t)2 * GM + (size_t)(b0 + 1) * SS) * HH + jown];
    }

    float zk0 = 0.f, zk1 = 0.f;   // warp0: z values carried reduce -> combine

    for (int t = 0; t < SS; t++) {
        const int par = t & 1;
        const uint32_t php = (uint32_t)((t >> 1) & 1);

        if (tid == 0) {
            mbar_expect(mb_rz + par * 8, 4096);
            mbar_expect(mb_h  + par * 8, 2048);
        }

        // ---- RZ partial matvec over local k-slice (h is local!) ----
        const u64* Hb0 = (const u64*)sH;          // k-pairs, batch 0
        const u64* Hb1 = (const u64*)(sH + 32);   // batch 1
        u64 az0 = 0, az1 = 0, ar0 = 0, ar1 = 0;
#pragma unroll
        for (int p = 0; p < 16; p++) {
            const u64 hp0 = Hb0[p], hp1 = Hb1[p];
            ffma2(az0, hp0, uz2[p]); ffma2(az1, hp1, uz2[p]);
            ffma2(ar0, hp0, ur2[p]); ffma2(ar1, hp1, ur2[p]);
        }
        {
            const u64 zval = pk(hsum(az0), hsum(az1));
            const u64 rval = pk(hsum(ar0), hsum(ar1));
            const uint32_t zo = (uint32_t)(OFF_PRZ * 4)
                              + (uint32_t)((((par * 2 + 0) * 32 + jl) * 8 + rank) * 8);
            const uint32_t ro = (uint32_t)(OFF_PRZ * 4)
                              + (uint32_t)((((par * 2 + 1) * 32 + jl) * 8 + rank) * 8);
            const uint32_t mo = (uint32_t)(OFF_MB * 4) + (uint32_t)(par * 8);
            st_async_b64(peer + zo, zval, peer + mo);
            st_async_b64(peer + ro, rval, peer + mo);
        }

        // ---- warp0: wait partials, reduce, gates, r*h ----
        if (tid < 32) {
            mbar_wait(mb_rz + par * 8, php);
            const u64* PZ = (const u64*)(smem + OFF_PRZ)
                          + ((size_t)(par * 2 + 0) * 32 + tid) * 8;
            const u64* PR = (const u64*)(smem + OFF_PRZ)
                          + ((size_t)(par * 2 + 1) * 32 + tid) * 8;
            ulonglong2 q0 = *(const ulonglong2*)(PZ + 0);
            ulonglong2 q1 = *(const ulonglong2*)(PZ + 2);
            ulonglong2 q2 = *(const ulonglong2*)(PZ + 4);
            ulonglong2 q3 = *(const ulonglong2*)(PZ + 6);
            u64 zs = addx2(addx2(addx2(q0.x, q0.y), addx2(q1.x, q1.y)),
                           addx2(addx2(q2.x, q2.y), addx2(q3.x, q3.y)));
            q0 = *(const ulonglong2*)(PR + 0);
            q1 = *(const ulonglong2*)(PR + 2);
            q2 = *(const ulonglong2*)(PR + 4);
            q3 = *(const ulonglong2*)(PR + 6);
            u64 rs = addx2(addx2(addx2(q0.x, q0.y), addx2(q1.x, q1.y)),
                           addx2(addx2(q2.x, q2.y), addx2(q3.x, q3.y)));
            float zb0, zb1, rb0, rb1;
            unpk(zs, zb0, zb1); unpk(rs, rb0, rb1);
            zk0 = __fdividef(1.f, 1.f + __expf(-(zb0 + pz0)));
            zk1 = __fdividef(1.f, 1.f + __expf(-(zb1 + pz1)));
            const float r0 = __fdividef(1.f, 1.f + __expf(-(rb0 + pr0)));
            const float r1 = __fdividef(1.f, 1.f + __expf(-(rb1 + pr1)));
            sRH[tid]      = r0 * hreg0;
            sRH[32 + tid] = r1 * hreg1;
            if (t + 1 < SS) {
                const int jown = kbase + tid;
                pz0 = g_gates[((size_t)0 * GM + (size_t)b0 * SS + t + 1) * HH + jown];
                pz1 = g_gates[((size_t)0 * GM + (size_t)(b0 + 1) * SS + t + 1) * HH + jown];
                pr0 = g_gates[((size_t)1 * GM + (size_t)b0 * SS + t + 1) * HH + jown];
                pr1 = g_gates[((size_t)1 * GM + (size_t)(b0 + 1) * SS + t + 1) * HH + jown];
            }
        }
        __syncthreads();

        // ---- H partial matvec over local k-slice (r*h is local!) ----
        const u64* Rb0 = (const u64*)sRH;
        const u64* Rb1 = (const u64*)(sRH + 32);
        u64 ah0 = 0, ah1 = 0;
#pragma unroll
        for (int p = 0; p < 16; p++) {
            ffma2(ah0, Rb0[p], uh2[p]);
            ffma2(ah1, Rb1[p], uh2[p]);
        }
        {
            const u64 hval = pk(hsum(ah0), hsum(ah1));
            const uint32_t ho = (uint32_t)(OFF_PH * 4)
                              + (uint32_t)(((par * 32 + jl) * 8 + rank) * 8);
            const uint32_t mo = (uint32_t)(OFF_MB * 4 + 16) + (uint32_t)(par * 8);
            st_async_b64(peer + ho, hval, peer + mo);
        }

        // ---- warp0: wait H partials, combine, output, update local h ----
        if (tid < 32) {
            mbar_wait(mb_h + par * 8, php);
            const u64* PH = (const u64*)(smem + OFF_PH)
                          + ((size_t)par * 32 + tid) * 8;
            ulonglong2 q0 = *(const ulonglong2*)(PH + 0);
            ulonglong2 q1 = *(const ulonglong2*)(PH + 2);
            ulonglong2 q2 = *(const ulonglong2*)(PH + 4);
            ulonglong2 q3 = *(const ulonglong2*)(PH + 6);
            u64 hs = addx2(addx2(addx2(q0.x, q0.y), addx2(q1.x, q1.y)),
                           addx2(addx2(q2.x, q2.y), addx2(q3.x, q3.y)));
            float sb0, sb1;
            unpk(hs, sb0, sb1);
            sb0 += phh0; sb1 += phh1;
            const float hw0 = 1.f - __fdividef(2.f, __expf(2.f * sb0) + 1.f);
            const float hw1 = 1.f - __fdividef(2.f, __expf(2.f * sb1) + 1.f);
            const float hn0 = fmaf(zk0, hw0 - hreg0, hreg0);
            const float hn1 = fmaf(zk1, hw1 - hreg1, hreg1);
            const int jown = kbase + tid;
            out[((size_t)b0 * SS + t) * HH + jown]       = hn0;
            out[((size_t)(b0 + 1) * SS + t) * HH + jown] = hn1;
            hreg0 = hn0; hreg1 = hn1;
            sH[tid]      = hn0;
            sH[32 + tid] = hn1;
            if (t + 1 < SS) {
                phh0 = g_gates[((size_t)2 * GM + (size_t)b0 * SS + t + 1) * HH + jown];
                phh1 = g_gates[((size_t)2 * GM + (size_t)(b0 + 1) * SS + t + 1) * HH + jown];
            }
        }
        __syncthreads();
    }
    cluster_sync_();   // no CTA exits while inbound traffic could be in flight
}

extern "C" void kernel_launch(void* const* d_in, const int* in_sizes, int n_in,
                              void* d_out, int out_size)
{
    (void)in_sizes; (void)n_in; (void)out_size;
    const float* x  = (const float*)d_in[0];
    const float* h0 = (const float*)d_in[1];
    const float* Wz = (const float*)d_in[2];
    const float* Uz = (const float*)d_in[3];
    const float* Wr = (const float*)d_in[4];
    const float* Ur = (const float*)d_in[5];
    const float* Wh = (const float*)d_in[6];
    const float* Uh = (const float*)d_in[7];
    float* out = (float*)d_out;

    dim3 ggrid(512, 12);
    gru_gemm<<<ggrid, 256>>>(x, Wz, Wr, Wh);

    cudaFuncSetAttribute(gru_scan,
                         cudaFuncAttributeMaxDynamicSharedMemorySize, SMEM_BYTES);
    gru_scan<<<GRID, NT, SMEM_BYTES>>>(h0, Uz, Ur, Uh, out);
}